// round 1
// baseline (speedup 1.0000x reference)
#include <cuda_runtime.h>
#include <cstdint>

// ---------------------------------------------------------------------------
// ResidualVectorQuantizer: B=32, T=2048, D=256, K=1024, NC=8
// N = B*T = 65536 rows.
// Outputs (inferred): quantized [N*D] f32, indices [N*NC] as f32, loss [1] f32
// ---------------------------------------------------------------------------

#define NROWS   65536
#define DDIM    256
#define KCB     1024
#define NCB     8
#define MT      128      // rows per block
#define NT      64       // codewords per chunk
#define NTHREADS 512
#define RSTRIDE 260      // padded row stride (floats) for R tile
#define NCHUNK  (KCB / NT)   // 16
#define NBLOCKS (NROWS / MT) // 512

// -------- device scratch (static allocation: no cudaMalloc allowed) --------
__device__ float  g_res[(size_t)NROWS * DDIM];   // 64 MB residual buffer
__device__ float  g_WT [(size_t)NCB * DDIM * KCB]; // 8 MB transposed codebooks [c][d][k]
__device__ float  g_ww [NCB * KCB];              // ||w||^2 per codeword
__device__ double g_lp [NCB * NBLOCKS];          // per-(stage,block) loss partials

// -------- shared memory layout (in floats) --------
#define SM_RT    0
#define SM_WT    (MT * RSTRIDE)               // 33280
#define SM_RR    (SM_WT + DDIM * NT)          // 49664
#define SM_WWS   (SM_RR + MT)                 // 49792
#define SM_BVAL  (SM_WWS + NT)                // 49856
#define SM_BIDX  (SM_BVAL + MT * 16)          // 51904
#define SM_QS    (SM_BIDX + MT * 16)          // 53952
#define SM_SIDX  (SM_QS + MT * 4)             // 54464
#define SM_LP    (SM_SIDX + MT)               // 54592
#define SM_TOTALF (SM_LP + 16)                // 54608 floats
#define SMEM_BYTES (SM_TOTALF * 4)            // 218432 bytes

// ---------------------------------------------------------------------------
// Transpose codebooks [c][k][d] -> g_WT [c][d][k]  (once per launch)
// ---------------------------------------------------------------------------
__global__ void rvq_transpose_kernel(const float* __restrict__ cb)
{
    __shared__ float tile[32][33];
    const int c  = blockIdx.z;
    const int d0 = blockIdx.x * 32;   // gridDim.x = DDIM/32 = 8
    const int k0 = blockIdx.y * 32;   // gridDim.y = KCB/32 = 32
    const float* src = cb + (size_t)c * KCB * DDIM;
    float* dst = g_WT + (size_t)c * DDIM * KCB;
    const int x = threadIdx.x;        // 0..31
    for (int r = threadIdx.y; r < 32; r += 8)
        tile[r][x] = src[(size_t)(k0 + r) * DDIM + d0 + x];
    __syncthreads();
    for (int r = threadIdx.y; r < 32; r += 8)
        dst[(size_t)(d0 + r) * KCB + k0 + x] = tile[x][r];
}

// ---------------------------------------------------------------------------
// ||w||^2 per codeword: one warp per codeword (8192 codewords)
// ---------------------------------------------------------------------------
__global__ void rvq_ww_kernel(const float* __restrict__ cb)
{
    const int warp = threadIdx.x >> 5;
    const int lane = threadIdx.x & 31;
    const int k = blockIdx.x * 8 + warp;           // grid 1024 * 8 warps = 8192
    const float* w = cb + (size_t)k * DDIM;
    float s = 0.f;
    #pragma unroll
    for (int t = 0; t < 8; t++) {
        float v = w[lane + 32 * t];
        s = fmaf(v, v, s);
    }
    #pragma unroll
    for (int o = 16; o; o >>= 1) s += __shfl_down_sync(0xffffffffu, s, o);
    if (lane == 0) g_ww[k] = s;
}

// ---------------------------------------------------------------------------
// Fused per-stage kernel: scores + argmin + residual/quantized update + loss
// ---------------------------------------------------------------------------
__global__ void __launch_bounds__(NTHREADS, 1)
rvq_stage_kernel(const float* __restrict__ z,
                 const float* __restrict__ cb,
                 float* __restrict__ qOut,
                 float* __restrict__ idxOut,   // may be null
                 int c)
{
    extern __shared__ float sm[];
    float* Rt   = sm + SM_RT;
    float* Wt   = sm + SM_WT;
    float* rr   = sm + SM_RR;
    float* wws  = sm + SM_WWS;
    float* bval = sm + SM_BVAL;
    int*   bidx = (int*)(sm + SM_BIDX);
    float* qs   = sm + SM_QS;
    int*   sIdx = (int*)(sm + SM_SIDX);
    float* lp   = sm + SM_LP;

    const int tid = threadIdx.x;
    const int tx  = tid & 15;      // col group (4 codewords)
    const int ty  = tid >> 4;      // row group (4 rows), 0..31
    const int blk = blockIdx.x;
    const long long rowbase = (long long)blk * MT;

    const float* resIn = (c == 0) ? z : g_res;
    const float* wtc = g_WT + (size_t)c * DDIM * KCB;
    const float* wwc = g_ww + c * KCB;
    const float* cbc = cb + (size_t)c * KCB * DDIM;

    // ---- load R tile (coalesced, padded stride) ----
    const float4* rin = (const float4*)(resIn + rowbase * DDIM);
    #pragma unroll
    for (int l = tid; l < MT * DDIM / 4; l += NTHREADS) {
        int row = l >> 6, c4 = l & 63;
        float4 v = rin[row * 64 + c4];
        *(float4*)(Rt + row * RSTRIDE + c4 * 4) = v;
    }
    __syncthreads();

    // ---- rr = ||r||^2 per row (exact value non-critical: uniform grid shift) ----
    {
        int row = tid >> 2, qq = tid & 3;
        const float* rp = Rt + row * RSTRIDE + qq * 64;
        float s = 0.f;
        #pragma unroll
        for (int d = 0; d < 64; d++) s = fmaf(rp[d], rp[d], s);
        qs[row * 4 + qq] = s;
    }
    __syncthreads();
    if (tid < MT)
        rr[tid] = qs[tid * 4] + qs[tid * 4 + 1] + qs[tid * 4 + 2] + qs[tid * 4 + 3];

    float bestv[4] = {3.0e38f, 3.0e38f, 3.0e38f, 3.0e38f};
    int   besti[4] = {0, 0, 0, 0};

    // ---- main loop over 16 codeword chunks ----
    for (int ck = 0; ck < NCHUNK; ck++) {
        __syncthreads();   // protect Wt/wws reuse; also publishes rr on ck==0
        const int kbase = ck * NT;
        // load W chunk, already d-major in g_WT: Wt[d][k], 256x64, no padding
        #pragma unroll
        for (int l = tid; l < DDIM * NT / 4; l += NTHREADS) {
            int d = l >> 4, k4 = l & 15;
            float4 v = *(const float4*)(wtc + (size_t)d * KCB + kbase + k4 * 4);
            *(float4*)(Wt + d * NT + k4 * 4) = v;
        }
        if (tid < NT) wws[tid] = wwc[kbase + tid];
        __syncthreads();

        float acc[4][4];
        #pragma unroll
        for (int i = 0; i < 4; i++)
            #pragma unroll
            for (int j = 0; j < 4; j++) acc[i][j] = 0.f;

        const float* rbase = Rt + (ty * 4) * RSTRIDE;
        #pragma unroll 2
        for (int dv = 0; dv < 64; dv++) {
            float a[4][4];   // [row i][d sub]
            float b[4][4];   // [d sub][col j]
            #pragma unroll
            for (int i = 0; i < 4; i++)
                *(float4*)&a[i][0] = *(const float4*)(rbase + i * RSTRIDE + dv * 4);
            #pragma unroll
            for (int dd = 0; dd < 4; dd++)
                *(float4*)&b[dd][0] = *(const float4*)(Wt + (dv * 4 + dd) * NT + tx * 4);
            #pragma unroll
            for (int i = 0; i < 4; i++)
                #pragma unroll
                for (int j = 0; j < 4; j++)
                    #pragma unroll
                    for (int dd = 0; dd < 4; dd++)
                        acc[i][j] = fmaf(a[i][dd], b[dd][j], acc[i][j]);
        }

        // update per-thread argmin: d2 = fl(fl(rr - 2*dot) + ww), ties -> lowest k
        #pragma unroll
        for (int i = 0; i < 4; i++) {
            float rri = rr[ty * 4 + i];
            #pragma unroll
            for (int j = 0; j < 4; j++) {
                float t  = fmaf(-2.0f, acc[i][j], rri);  // == fl(rr - fl(2*dot))
                float d2 = t + wws[tx * 4 + j];
                int   kg = kbase + tx * 4 + j;
                if (d2 < bestv[i]) { bestv[i] = d2; besti[i] = kg; }
            }
        }
    }

    // ---- cross-thread argmin merge (lexicographic: val, then index) ----
    #pragma unroll
    for (int i = 0; i < 4; i++) {
        bval[(ty * 4 + i) * 16 + tx] = bestv[i];
        bidx[(ty * 4 + i) * 16 + tx] = besti[i];
    }
    __syncthreads();
    if (tid < MT) {
        float bv = bval[tid * 16];
        int   bi = bidx[tid * 16];
        #pragma unroll
        for (int t = 1; t < 16; t++) {
            float v = bval[tid * 16 + t];
            int  id = bidx[tid * 16 + t];
            if (v < bv || (v == bv && id < bi)) { bv = v; bi = id; }
        }
        sIdx[tid] = bi;
        if (idxOut) idxOut[(rowbase + tid) * NCB + c] = (float)bi;
    }
    __syncthreads();

    // ---- epilogue: residual / quantized update + loss partial ----
    {
        int lr = tid >> 2, qq = tid & 3;
        long long grow = rowbase + lr;
        int bi = sIdx[lr];
        const float* wrow = cbc + (size_t)bi * DDIM;
        float* ro = g_res + grow * DDIM;
        float* qo = qOut + grow * DDIM;
        float lsum = 0.f;
        #pragma unroll
        for (int t = 0; t < 16; t++) {
            int d4 = qq + 4 * t;                    // interleaved for coalescing
            float4 w4 = *(const float4*)(wrow + d4 * 4);
            float4 r4 = *(const float4*)(Rt + lr * RSTRIDE + d4 * 4);
            float4 nr;
            nr.x = r4.x - w4.x; nr.y = r4.y - w4.y;
            nr.z = r4.z - w4.z; nr.w = r4.w - w4.w;
            *(float4*)(ro + d4 * 4) = nr;
            float4 qv;
            if (c == 0) {
                qv = w4;
            } else {
                float4 qp = *(const float4*)(qo + d4 * 4);
                qv.x = qp.x + w4.x; qv.y = qp.y + w4.y;
                qv.z = qp.z + w4.z; qv.w = qp.w + w4.w;
            }
            *(float4*)(qo + d4 * 4) = qv;
            lsum = fmaf(nr.x, nr.x, lsum);
            lsum = fmaf(nr.y, nr.y, lsum);
            lsum = fmaf(nr.z, nr.z, lsum);
            lsum = fmaf(nr.w, nr.w, lsum);
        }
        #pragma unroll
        for (int o = 16; o; o >>= 1) lsum += __shfl_down_sync(0xffffffffu, lsum, o);
        if ((tid & 31) == 0) lp[tid >> 5] = lsum;
    }
    __syncthreads();
    if (tid == 0) {
        double t = 0.0;
        #pragma unroll
        for (int w = 0; w < 16; w++) t += (double)lp[w];
        g_lp[c * NBLOCKS + blk] = t;   // plain store: deterministic, no atomics
    }
}

// ---------------------------------------------------------------------------
// Final deterministic loss reduction
// ---------------------------------------------------------------------------
__global__ void rvq_loss_kernel(float* __restrict__ out, int lossOff)
{
    if (lossOff < 0) return;
    __shared__ double sd[256];
    int tid = threadIdx.x;
    double s = 0.0;
    for (int i = tid; i < NCB * NBLOCKS; i += 256) s += g_lp[i];
    sd[tid] = s;
    __syncthreads();
    for (int o = 128; o; o >>= 1) {
        if (tid < o) sd[tid] += sd[tid + o];
        __syncthreads();
    }
    if (tid == 0)
        out[lossOff] = (float)(sd[0] / (double)((long long)NROWS * DDIM));
}

// ---------------------------------------------------------------------------
extern "C" void kernel_launch(void* const* d_in, const int* in_sizes, int n_in,
                              void* d_out, int out_size)
{
    const float* z  = (const float*)d_in[0];
    const float* cb = (const float*)d_in[1];
    float* out = (float*)d_out;

    static bool attr_set = false;
    if (!attr_set) {
        cudaFuncSetAttribute(rvq_stage_kernel,
                             cudaFuncAttributeMaxDynamicSharedMemorySize,
                             SMEM_BYTES);
        attr_set = true;
    }

    const int NZ   = NROWS * DDIM;   // 16777216
    const int NIDX = NROWS * NCB;    // 524288
    float* idxOut = nullptr;
    int lossOff = -1;
    if (out_size >= NZ + NIDX + 1) { idxOut = out + NZ; lossOff = NZ + NIDX; }
    else if (out_size == NZ + NIDX) { idxOut = out + NZ; }
    else if (out_size == NZ + 1)    { lossOff = NZ; }

    {
        dim3 tb(32, 8);
        dim3 tg(DDIM / 32, KCB / 32, NCB);
        rvq_transpose_kernel<<<tg, tb>>>(cb);
    }
    rvq_ww_kernel<<<KCB * NCB / 8 / 32 * 32, 256>>>(cb);   // 1024 blocks x 8 warps

    for (int c = 0; c < NCB; c++)
        rvq_stage_kernel<<<NBLOCKS, NTHREADS, SMEM_BYTES>>>(z, cb, out, idxOut, c);

    rvq_loss_kernel<<<1, 256>>>(out, lossOff);
}